// round 1
// baseline (speedup 1.0000x reference)
#include <cuda_runtime.h>
#include <cstdint>

#define BATCH 1024
#define TLEN  4096
#define DIN   8
#define PF    8        // prefetch depth (register pipeline)

// Scratch: gx0[t][b] = W_ih0 . x[b,t,:] + b_ih0, padded float4, padded in t for prefetch overrun
__device__ float4 g_gx[(TLEN + 2 * PF) * BATCH];

// ---------------------------------------------------------------------------
// Fast-but-accurate transcendentals (MUFU ex2/rcp, ~2^-22 rel err)
// ---------------------------------------------------------------------------
__device__ __forceinline__ float fast_ex2(float x) {
    float y; asm("ex2.approx.f32 %0, %1;" : "=f"(y) : "f"(x)); return y;
}
__device__ __forceinline__ float fast_rcp(float x) {
    float y; asm("rcp.approx.f32 %0, %1;" : "=f"(y) : "f"(x)); return y;
}
__device__ __forceinline__ float sigmoid_f(float x) {
    // 1 / (1 + 2^(-x*log2 e))
    float e = fast_ex2(x * -1.4426950408889634f);
    return fast_rcp(1.0f + e);
}
__device__ __forceinline__ float tanh_f(float x) {
    // 1 - 2/(1 + 2^(2x*log2 e)) ; saturates correctly at +-inf
    float e = fast_ex2(x * 2.8853900817779268f);
    return fmaf(-2.0f, fast_rcp(1.0f + e), 1.0f);
}

// One GRU cell step (hidden=1). Gate order r,z,n (PyTorch).
__device__ __forceinline__ float gru_step(float h, float gr, float gz, float gn,
                                          float wr, float wz, float wn,
                                          float br, float bz, float bn) {
    float ghr = fmaf(h, wr, br);
    float ghz = fmaf(h, wz, bz);
    float ghn = fmaf(h, wn, bn);
    float r = sigmoid_f(gr + ghr);
    float z = sigmoid_f(gz + ghz);
    float n = tanh_f(fmaf(r, ghn, gn));
    // (1-z)*n + z*h = n + z*(h-n)
    return fmaf(z, h - n, n);
}

// ---------------------------------------------------------------------------
// Kernel 1: precompute layer-0 input gates gx0 = W_ih0 x + b_ih0
//   thread idx = t*BATCH + b  (b fastest) -> coalesced float4 writes,
//   x reads are exact 32B sectors per lane.
// ---------------------------------------------------------------------------
__global__ void gx_kernel(const float* __restrict__ x,
                          const float* __restrict__ wih0,
                          const float* __restrict__ bih0) {
    int idx = blockIdx.x * blockDim.x + threadIdx.x;
    if (idx >= BATCH * TLEN) return;
    int t = idx >> 10;          // / BATCH
    int b = idx & (BATCH - 1);  // % BATCH

    const float4* xr = reinterpret_cast<const float4*>(x + ((size_t)b * TLEN + t) * DIN);
    float4 a0 = __ldg(xr);
    float4 a1 = __ldg(xr + 1);

    float g[3];
#pragma unroll
    for (int gi = 0; gi < 3; gi++) {
        const float* w = wih0 + gi * DIN;
        float s = __ldg(bih0 + gi);
        s = fmaf(a0.x, __ldg(w + 0), s);
        s = fmaf(a0.y, __ldg(w + 1), s);
        s = fmaf(a0.z, __ldg(w + 2), s);
        s = fmaf(a0.w, __ldg(w + 3), s);
        s = fmaf(a1.x, __ldg(w + 4), s);
        s = fmaf(a1.y, __ldg(w + 5), s);
        s = fmaf(a1.z, __ldg(w + 6), s);
        s = fmaf(a1.w, __ldg(w + 7), s);
        g[gi] = s;
    }
    g_gx[idx] = make_float4(g[0], g[1], g[2], 0.0f);
}

// ---------------------------------------------------------------------------
// Kernel 2: sequential scan, 1 thread per batch element.
// Three layers time-skewed inside the thread for ILP:
//   iter s: layer0 @ t=s, layer1 @ t=s-1, layer2 @ t=s-2.
// ---------------------------------------------------------------------------
__global__ void __launch_bounds__(32, 1)
scan_kernel(const float* __restrict__ whh0, const float* __restrict__ bhh0,
            const float* __restrict__ wih1, const float* __restrict__ whh1,
            const float* __restrict__ bih1, const float* __restrict__ bhh1,
            const float* __restrict__ wih2, const float* __restrict__ whh2,
            const float* __restrict__ bih2, const float* __restrict__ bhh2,
            float* __restrict__ out) {
    int b = blockIdx.x * 32 + threadIdx.x;

    // Layer 0 recurrent weights
    float w0r = __ldg(whh0 + 0), w0z = __ldg(whh0 + 1), w0n = __ldg(whh0 + 2);
    float c0r = __ldg(bhh0 + 0), c0z = __ldg(bhh0 + 1), c0n = __ldg(bhh0 + 2);
    // Layer 1
    float u1r = __ldg(wih1 + 0), u1z = __ldg(wih1 + 1), u1n = __ldg(wih1 + 2);
    float w1r = __ldg(whh1 + 0), w1z = __ldg(whh1 + 1), w1n = __ldg(whh1 + 2);
    float d1r = __ldg(bih1 + 0), d1z = __ldg(bih1 + 1), d1n = __ldg(bih1 + 2);
    float c1r = __ldg(bhh1 + 0), c1z = __ldg(bhh1 + 1), c1n = __ldg(bhh1 + 2);
    // Layer 2
    float u2r = __ldg(wih2 + 0), u2z = __ldg(wih2 + 1), u2n = __ldg(wih2 + 2);
    float w2r = __ldg(whh2 + 0), w2z = __ldg(whh2 + 1), w2n = __ldg(whh2 + 2);
    float d2r = __ldg(bih2 + 0), d2z = __ldg(bih2 + 1), d2n = __ldg(bih2 + 2);
    float c2r = __ldg(bhh2 + 0), c2z = __ldg(bhh2 + 1), c2n = __ldg(bhh2 + 2);

    float h0 = 0.0f, h1 = 0.0f, h2 = 0.0f;
    float o0 = 0.0f, o1 = 0.0f;   // layer outputs from previous iteration

    // Register prefetch pipeline for gx0
    float4 buf[PF];
#pragma unroll
    for (int j = 0; j < PF; j++) buf[j] = g_gx[j * BATCH + b];

    // T + 2 iterations needed (skew); run to T+PF so the block count is a
    // multiple of PF (4096+8 = 513*8). Guards make extra iterations no-ops.
    for (int sb = 0; sb < TLEN + PF; sb += PF) {
#pragma unroll
        for (int j = 0; j < PF; j++) {
            int s = sb + j;
            float4 g = buf[j];
            buf[j] = g_gx[(s + PF) * BATCH + b];   // stays in-bounds via padding

            float i1 = o0, i2 = o1;

            if (s < TLEN) {
                h0 = gru_step(h0, g.x, g.y, g.z, w0r, w0z, w0n, c0r, c0z, c0n);
            }
            if (s >= 1 && s < TLEN + 1) {
                float gr = fmaf(i1, u1r, d1r);
                float gz = fmaf(i1, u1z, d1z);
                float gn = fmaf(i1, u1n, d1n);
                h1 = gru_step(h1, gr, gz, gn, w1r, w1z, w1n, c1r, c1z, c1n);
            }
            if (s >= 2 && s < TLEN + 2) {
                float gr = fmaf(i2, u2r, d2r);
                float gz = fmaf(i2, u2z, d2z);
                float gn = fmaf(i2, u2n, d2n);
                h2 = gru_step(h2, gr, gz, gn, w2r, w2z, w2n, c2r, c2z, c2n);
            }
            o0 = h0; o1 = h1;
        }
    }
    out[b] = h2;
}

// ---------------------------------------------------------------------------
extern "C" void kernel_launch(void* const* d_in, const int* in_sizes, int n_in,
                              void* d_out, int out_size) {
    const float* x    = (const float*)d_in[0];
    const float* wih0 = (const float*)d_in[1];
    const float* whh0 = (const float*)d_in[2];
    const float* bih0 = (const float*)d_in[3];
    const float* bhh0 = (const float*)d_in[4];
    const float* wih1 = (const float*)d_in[5];
    const float* whh1 = (const float*)d_in[6];
    const float* bih1 = (const float*)d_in[7];
    const float* bhh1 = (const float*)d_in[8];
    const float* wih2 = (const float*)d_in[9];
    const float* whh2 = (const float*)d_in[10];
    const float* bih2 = (const float*)d_in[11];
    const float* bhh2 = (const float*)d_in[12];
    float* out = (float*)d_out;

    gx_kernel<<<(BATCH * TLEN + 255) / 256, 256>>>(x, wih0, bih0);
    scan_kernel<<<BATCH / 32, 32>>>(whh0, bhh0,
                                    wih1, whh1, bih1, bhh1,
                                    wih2, whh2, bih2, bhh2, out);
}

// round 2
// speedup vs baseline: 1.7304x; 1.7304x over previous
#include <cuda_runtime.h>
#include <cstdint>

#define BATCH 1024
#define TLEN  4096
#define DIN   8
#define PF    8        // prefetch depth (register pipeline)

#define NL2E  (-1.4426950408889634f)   // -log2(e)
#define P2L2E ( 2.8853900817779268f)   //  2*log2(e)

// Scratch: pre-scaled layer-0 input gates, [t][b] layout, float4-padded.
// Padded in t beyond TLEN for branchless epilogue + prefetch overrun.
// (__device__ globals are zero-initialized; gx_kernel never writes the pad.)
__device__ float4 g_gx[(TLEN + 2 * PF) * BATCH];

__device__ __forceinline__ float fast_ex2(float x) {
    float y; asm("ex2.approx.f32 %0, %1;" : "=f"(y) : "f"(x)); return y;
}
__device__ __forceinline__ float fast_rcp(float x) {
    float y; asm("rcp.approx.f32 %0, %1;" : "=f"(y) : "f"(x)); return y;
}

// GRU cell, hidden=1, with all log2e scalings pre-folded.
//  grs = -L2E*(gate_r input incl. its bias), gzs likewise,
//  gn2 = 2L2E*(gate_n feedforward part), wn2/cn2 = 2L2E*(w_hh_n / b_hh_n).
// sigma(a) = rcp(1 + ex2(-L2E*a));  tanh(a) = 1 - 2*rcp(1 + ex2(2*L2E*a))
__device__ __forceinline__ float gru_cell(float h,
                                          float grs, float gzs, float gn2,
                                          float wrs, float wzs,
                                          float wn2, float cn2) {
    float yr = fmaf(h, wrs, grs);
    float yz = fmaf(h, wzs, gzs);
    float er = fast_ex2(yr);
    float ez = fast_ex2(yz);
    float r  = fast_rcp(1.0f + er);
    float z  = fast_rcp(1.0f + ez);
    float ghn2 = fmaf(h, wn2, cn2);
    float yn = fmaf(r, ghn2, gn2);
    float en = fast_ex2(yn);
    float q  = fast_rcp(1.0f + en);
    float n  = fmaf(-2.0f, q, 1.0f);
    return fmaf(z, h - n, n);          // (1-z)n + z h
}

// ---------------------------------------------------------------------------
// Kernel 1: gx0 = W_ih0 x + b_ih0, pre-scaled by -L2E / -L2E / 2L2E.
// ---------------------------------------------------------------------------
__global__ void gx_kernel(const float* __restrict__ x,
                          const float* __restrict__ wih0,
                          const float* __restrict__ bih0) {
    int idx = blockIdx.x * blockDim.x + threadIdx.x;
    if (idx >= BATCH * TLEN) return;
    int t = idx >> 10;          // / BATCH
    int b = idx & (BATCH - 1);  // % BATCH

    const float4* xr = reinterpret_cast<const float4*>(x + ((size_t)b * TLEN + t) * DIN);
    float4 a0 = __ldg(xr);
    float4 a1 = __ldg(xr + 1);

    float g[3];
#pragma unroll
    for (int gi = 0; gi < 3; gi++) {
        const float* w = wih0 + gi * DIN;
        float s = __ldg(bih0 + gi);
        s = fmaf(a0.x, __ldg(w + 0), s);
        s = fmaf(a0.y, __ldg(w + 1), s);
        s = fmaf(a0.z, __ldg(w + 2), s);
        s = fmaf(a0.w, __ldg(w + 3), s);
        s = fmaf(a1.x, __ldg(w + 4), s);
        s = fmaf(a1.y, __ldg(w + 5), s);
        s = fmaf(a1.z, __ldg(w + 6), s);
        s = fmaf(a1.w, __ldg(w + 7), s);
        g[gi] = s;
    }
    g_gx[idx] = make_float4(NL2E * g[0], NL2E * g[1], P2L2E * g[2], 0.0f);
}

// ---------------------------------------------------------------------------
// Kernel 2: sequential scan, 1 thread per batch element, 3 layers time-skewed.
// Iteration s: layer0@t=s, layer1@t=s-1, layer2@t=s-2. Prologue peeled
// (s=0,1); main loop s=2..4097 is branch-free; the spurious layer-0/1 updates
// at s>=4096 consume zero-padded gx rows and never reach the layer-2 output.
// ---------------------------------------------------------------------------
__global__ void __launch_bounds__(32, 1)
scan_kernel(const float* __restrict__ whh0, const float* __restrict__ bhh0,
            const float* __restrict__ wih1, const float* __restrict__ whh1,
            const float* __restrict__ bih1, const float* __restrict__ bhh1,
            const float* __restrict__ wih2, const float* __restrict__ whh2,
            const float* __restrict__ bih2, const float* __restrict__ bhh2,
            float* __restrict__ out) {
    int b = blockIdx.x * 32 + threadIdx.x;

    // ---- pre-scaled constants ------------------------------------------------
    // Layer 0 recurrent
    float w0rs = NL2E * __ldg(whh0 + 0), w0zs = NL2E * __ldg(whh0 + 1);
    float w0n2 = P2L2E * __ldg(whh0 + 2);
    float c0rs = NL2E * __ldg(bhh0 + 0), c0zs = NL2E * __ldg(bhh0 + 1);
    float c0n2 = P2L2E * __ldg(bhh0 + 2);
    // Layer 1
    float u1rs = NL2E * __ldg(wih1 + 0), u1zs = NL2E * __ldg(wih1 + 1);
    float u1n2 = P2L2E * __ldg(wih1 + 2);
    float d1rs = NL2E * (__ldg(bih1 + 0) + __ldg(bhh1 + 0));
    float d1zs = NL2E * (__ldg(bih1 + 1) + __ldg(bhh1 + 1));
    float d1n2 = P2L2E * __ldg(bih1 + 2);
    float w1rs = NL2E * __ldg(whh1 + 0), w1zs = NL2E * __ldg(whh1 + 1);
    float w1n2 = P2L2E * __ldg(whh1 + 2);
    float c1n2 = P2L2E * __ldg(bhh1 + 2);
    // Layer 2
    float u2rs = NL2E * __ldg(wih2 + 0), u2zs = NL2E * __ldg(wih2 + 1);
    float u2n2 = P2L2E * __ldg(wih2 + 2);
    float d2rs = NL2E * (__ldg(bih2 + 0) + __ldg(bhh2 + 0));
    float d2zs = NL2E * (__ldg(bih2 + 1) + __ldg(bhh2 + 1));
    float d2n2 = P2L2E * __ldg(bih2 + 2);
    float w2rs = NL2E * __ldg(whh2 + 0), w2zs = NL2E * __ldg(whh2 + 1);
    float w2n2 = P2L2E * __ldg(whh2 + 2);
    float c2n2 = P2L2E * __ldg(bhh2 + 2);

    float h0, h1, h2 = 0.0f;
    float o0, o1;

    // ---- prologue: s = 0 (layer0 only) --------------------------------------
    {
        float4 g = g_gx[0 * BATCH + b];
        h0 = gru_cell(0.0f, g.x + c0rs, g.y + c0zs, g.z,
                      w0rs, w0zs, w0n2, c0n2);
        o0 = h0;
    }
    // ---- prologue: s = 1 (layer0 + layer1 first step) -----------------------
    {
        float4 g = g_gx[1 * BATCH + b];
        float i1 = o0;
        h0 = gru_cell(h0, g.x + c0rs, g.y + c0zs, g.z,
                      w0rs, w0zs, w0n2, c0n2);
        h1 = gru_cell(0.0f,
                      fmaf(i1, u1rs, d1rs), fmaf(i1, u1zs, d1zs),
                      fmaf(i1, u1n2, d1n2),
                      w1rs, w1zs, w1n2, c1n2);
        o0 = h0; o1 = h1;
    }

    // ---- register prefetch pipeline, rows 2..2+PF-1 -------------------------
    float4 buf[PF];
#pragma unroll
    for (int j = 0; j < PF; j++) buf[j] = g_gx[(2 + j) * BATCH + b];

    // ---- main loop: s = 2 .. 4097, branch-free ------------------------------
    for (int sb = 2; sb < TLEN + 2; sb += PF) {
#pragma unroll
        for (int j = 0; j < PF; j++) {
            int s = sb + j;
            float4 g = buf[j];
            buf[j] = g_gx[(s + PF) * BATCH + b];   // pad keeps this in-bounds

            float i1 = o0, i2 = o1;

            h0 = gru_cell(h0, g.x + c0rs, g.y + c0zs, g.z,
                          w0rs, w0zs, w0n2, c0n2);
            h1 = gru_cell(h1,
                          fmaf(i1, u1rs, d1rs), fmaf(i1, u1zs, d1zs),
                          fmaf(i1, u1n2, d1n2),
                          w1rs, w1zs, w1n2, c1n2);
            h2 = gru_cell(h2,
                          fmaf(i2, u2rs, d2rs), fmaf(i2, u2zs, d2zs),
                          fmaf(i2, u2n2, d2n2),
                          w2rs, w2zs, w2n2, c2n2);
            o0 = h0; o1 = h1;
        }
    }
    out[b] = h2;
}

// ---------------------------------------------------------------------------
extern "C" void kernel_launch(void* const* d_in, const int* in_sizes, int n_in,
                              void* d_out, int out_size) {
    const float* x    = (const float*)d_in[0];
    const float* wih0 = (const float*)d_in[1];
    const float* whh0 = (const float*)d_in[2];
    const float* bih0 = (const float*)d_in[3];
    const float* bhh0 = (const float*)d_in[4];
    const float* wih1 = (const float*)d_in[5];
    const float* whh1 = (const float*)d_in[6];
    const float* bih1 = (const float*)d_in[7];
    const float* bhh1 = (const float*)d_in[8];
    const float* wih2 = (const float*)d_in[9];
    const float* whh2 = (const float*)d_in[10];
    const float* bih2 = (const float*)d_in[11];
    const float* bhh2 = (const float*)d_in[12];
    float* out = (float*)d_out;

    gx_kernel<<<(BATCH * TLEN + 255) / 256, 256>>>(x, wih0, bih0);
    scan_kernel<<<BATCH / 32, 32>>>(whh0, bhh0,
                                    wih1, whh1, bih1, bhh1,
                                    wih2, whh2, bih2, bhh2, out);
}